// round 11
// baseline (speedup 1.0000x reference)
#include <cuda_runtime.h>
#include <math.h>

#define Nn 1024
#define Ff 64
#define ALPHA 0.2f

// scratch
__device__ __align__(16) float g_Wh[Nn * Ff];
__device__ float g_e1[Nn];
__device__ float g_e2[Nn];

// ---------------------------------------------------------------------------
// k1: Wh = h @ W ; e1 = Wh@a1 ; e2 = Wh@a2. grid 256 (4 rows/block),
// SMEM-staged W, 1 output/thread.
// ---------------------------------------------------------------------------
__global__ __launch_bounds__(256) void gat_k1(const float* __restrict__ h,
                                              const float* __restrict__ W,
                                              const float* __restrict__ a) {
    __shared__ float Ws[Ff * Ff];
    __shared__ float hs[4 * Ff];
    __shared__ float a1s[Ff], a2s[Ff];
    __shared__ float es1[8], es2[8];
    int t = threadIdx.x;
    int row0 = blockIdx.x * 4;

#pragma unroll
    for (int k = 0; k < 4; k++)
        ((float4*)Ws)[t + k * 256] = ((const float4*)W)[t + k * 256];
    hs[t] = h[row0 * Ff + t];
    if (t < Ff) { a1s[t] = a[t]; a2s[t] = a[Ff + t]; }
    __syncthreads();

    int ii = t >> 6;
    int f  = t & 63;
    float acc = 0.f;
#pragma unroll
    for (int k = 0; k < Ff; k++)
        acc += hs[ii * Ff + k] * Ws[k * Ff + f];
    int row = row0 + ii;
    g_Wh[row * Ff + f] = acc;

    float p1 = acc * a1s[f];
    float p2 = acc * a2s[f];
#pragma unroll
    for (int o = 16; o; o >>= 1) {
        p1 += __shfl_xor_sync(0xffffffffu, p1, o);
        p2 += __shfl_xor_sync(0xffffffffu, p2, o);
    }
    int w = t >> 5;
    if ((t & 31) == 0) { es1[w] = p1; es2[w] = p2; }
    __syncthreads();
    if (t < 4) {
        g_e1[row0 + t] = es1[2 * t] + es1[2 * t + 1];
        g_e2[row0 + t] = es2[2 * t] + es2[2 * t + 1];
    }
}

// ---------------------------------------------------------------------------
// k2: fused attention: out = elu( (P@Wh) / rowsum ), unnormalized softmax.
// grid 256 (4 rows/block), 512 threads (2 CTA/SM).
// PDL: launched with programmatic stream serialization; the 4MB adj prologue
// (independent of k1) runs concurrently with k1, then griddepcontrol.wait
// gates the reads of k1's outputs (e1/e2/Wh).
// p-tiles ping-pong between two SMEM buffers (write jt+1 after GEMM jt, no
// WAR barrier). GEMM: thread (fi=t&15, jg=(t>>4)&31), Wh double-buffered
// LDG.128, p dup-pairs broadcast LDS.128, fma.f32x2 accumulators.
// ---------------------------------------------------------------------------
__global__ __launch_bounds__(512, 2) void gat_k2(const int* __restrict__ adj,
                                                 float* __restrict__ out) {
    __shared__ __align__(16) float ps[2][256 * 8];   // 16KB ping-pong p tiles
    __shared__ __align__(16) float red[32 * 264];    // 33.8KB split buffer
    __shared__ float red2[256];
    __shared__ float wpart[16][2];
    __shared__ float dfin[4];

    int t = threadIdx.x;
    int r0 = blockIdx.x * 4;
    int half = t >> 8;               // 0: rows 0,1 ; 1: rows 2,3
    int jc = t & 255;                // j within tile
    int fi = t & 15;
    int jg = (t >> 4) & 31;

    // ---- adj prologue (input-only, overlaps k1 via PDL) ----
    int av[4][2];
#pragma unroll
    for (int jt = 0; jt < 4; jt++) {
        const int* ac = adj + jt * 256 + jc;
        av[jt][0] = __ldg(ac + (size_t)(r0 + half * 2 + 0) * Nn);
        av[jt][1] = __ldg(ac + (size_t)(r0 + half * 2 + 1) * Nn);
    }

    // ---- wait for k1's outputs to be visible ----
    asm volatile("griddepcontrol.wait;" ::: "memory");

    float e2v[4];
#pragma unroll
    for (int jt = 0; jt < 4; jt++)
        e2v[jt] = __ldg(&g_e2[jt * 256 + jc]);
    float e1a = __ldg(&g_e1[r0 + half * 2 + 0]);
    float e1b = __ldg(&g_e1[r0 + half * 2 + 1]);

    float da = 0.f, db = 0.f;
    unsigned long long acc_lo[4] = {0ull, 0ull, 0ull, 0ull};
    unsigned long long acc_hi[4] = {0ull, 0ull, 0ull, 0ull};
    const ulonglong2* WhL = (const ulonglong2*)g_Wh;

    // ---- p tile 0 into ps[0] ----
    {
        float e2 = e2v[0];
        float s0 = e1a + e2; s0 = (s0 > 0.f) ? s0 : ALPHA * s0;
        float s1 = e1b + e2; s1 = (s1 > 0.f) ? s1 : ALPHA * s1;
        float p0 = (av[0][0] > 0) ? __expf(s0) : 0.f;
        float p1 = (av[0][1] > 0) ? __expf(s1) : 0.f;
        da += p0; db += p1;
        *(float4*)&ps[0][jc * 8 + half * 4] = make_float4(p0, p0, p1, p1);
    }

    // prefetch first Wh batch (tile 0, steps 0..3)
    ulonglong2 whbuf[4];
#pragma unroll
    for (int kk = 0; kk < 4; kk++)
        whbuf[kk] = WhL[(size_t)(kk * 32 + jg) * 16 + fi];
    __syncthreads();

#pragma unroll
    for (int jt = 0; jt < 4; jt++) {
        const float* psb = ps[jt & 1];

        // ---- GEMM: 8 j-steps in 2 double-buffered batches ----
#pragma unroll
        for (int kb = 0; kb < 2; kb++) {
            ulonglong2 c[4];
#pragma unroll
            for (int kk = 0; kk < 4; kk++) c[kk] = whbuf[kk];

            if (kb == 0) {
#pragma unroll
                for (int kk = 0; kk < 4; kk++)
                    whbuf[kk] = WhL[(size_t)(jt * 256 + (4 + kk) * 32 + jg) * 16 + fi];
            } else if (jt < 3) {
#pragma unroll
                for (int kk = 0; kk < 4; kk++)
                    whbuf[kk] = WhL[(size_t)((jt + 1) * 256 + kk * 32 + jg) * 16 + fi];
            }

#pragma unroll
            for (int kk = 0; kk < 4; kk++) {
                int j = (kb * 4 + kk) * 32 + jg;
                ulonglong2 wh = c[kk];
                ulonglong2 pA = *(const ulonglong2*)&psb[j * 8];
                ulonglong2 pB = *(const ulonglong2*)&psb[j * 8 + 4];
                asm("fma.rn.f32x2 %0,%1,%2,%0;" : "+l"(acc_lo[0]) : "l"(pA.x), "l"(wh.x));
                asm("fma.rn.f32x2 %0,%1,%2,%0;" : "+l"(acc_hi[0]) : "l"(pA.x), "l"(wh.y));
                asm("fma.rn.f32x2 %0,%1,%2,%0;" : "+l"(acc_lo[1]) : "l"(pA.y), "l"(wh.x));
                asm("fma.rn.f32x2 %0,%1,%2,%0;" : "+l"(acc_hi[1]) : "l"(pA.y), "l"(wh.y));
                asm("fma.rn.f32x2 %0,%1,%2,%0;" : "+l"(acc_lo[2]) : "l"(pB.x), "l"(wh.x));
                asm("fma.rn.f32x2 %0,%1,%2,%0;" : "+l"(acc_hi[2]) : "l"(pB.x), "l"(wh.y));
                asm("fma.rn.f32x2 %0,%1,%2,%0;" : "+l"(acc_lo[3]) : "l"(pB.y), "l"(wh.x));
                asm("fma.rn.f32x2 %0,%1,%2,%0;" : "+l"(acc_hi[3]) : "l"(pB.y), "l"(wh.y));
            }
        }

        // ---- write p tile jt+1 into the other buffer (no WAR hazard) ----
        if (jt < 3) {
            float e2 = e2v[jt + 1];
            float s0 = e1a + e2; s0 = (s0 > 0.f) ? s0 : ALPHA * s0;
            float s1 = e1b + e2; s1 = (s1 > 0.f) ? s1 : ALPHA * s1;
            float p0 = (av[jt + 1][0] > 0) ? __expf(s0) : 0.f;
            float p1 = (av[jt + 1][1] > 0) ? __expf(s1) : 0.f;
            da += p0; db += p1;
            *(float4*)&ps[(jt + 1) & 1][jc * 8 + half * 4] = make_float4(p0, p0, p1, p1);
        }
        __syncthreads();
    }

    // ---- dsum: warp-reduce ----
#pragma unroll
    for (int o = 16; o; o >>= 1) {
        da += __shfl_xor_sync(0xffffffffu, da, o);
        db += __shfl_xor_sync(0xffffffffu, db, o);
    }
    if ((t & 31) == 0) {
        int w = t >> 5;
        wpart[w][0] = da;
        wpart[w][1] = db;
    }

    // ---- write register tiles to red[jg] ----
#pragma unroll
    for (int ii = 0; ii < 4; ii++) {
        float2 lo = *(float2*)&acc_lo[ii];
        float2 hi = *(float2*)&acc_hi[ii];
        *(float4*)&red[jg * 264 + ii * 64 + fi * 4] = make_float4(lo.x, lo.y, hi.x, hi.y);
    }
    __syncthreads();

    // ---- combine dsums ----
    if (t < 4) {
        int hh = t >> 1, rr = t & 1;
        float dd = 0.f;
#pragma unroll
        for (int w2 = 0; w2 < 8; w2++) dd += wpart[hh * 8 + w2][rr];
        dfin[t] = dd;
    }

    // ---- reduce 32 splits: each half sums 16, then combine ----
    {
        int e = t & 255;
        float val = 0.f;
#pragma unroll
        for (int g = 0; g < 16; g++)
            val += red[(half * 16 + g) * 264 + e];
        if (half == 1) red2[e] = val;
        __syncthreads();
        if (half == 0) {
            val += red2[e];
            int oii = e >> 6;
            int of  = e & 63;
            float r = val / dfin[oii];
            r = (r > 0.f) ? r : expm1f(r);
            out[(size_t)(r0 + oii) * Ff + of] = r;
        }
    }
}

// ---------------------------------------------------------------------------
extern "C" void kernel_launch(void* const* d_in, const int* in_sizes, int n_in,
                              void* d_out, int out_size) {
    const float* h   = (const float*)d_in[0];
    const int*   adj = (const int*)d_in[1];
    const float* W   = (const float*)d_in[2];
    const float* a   = (const float*)d_in[3];
    float* out = (float*)d_out;

    gat_k1<<<256, 256>>>(h, W, a);

    // k2 with programmatic dependent launch: its adj prologue overlaps k1.
    cudaLaunchConfig_t cfg = {};
    cfg.gridDim  = dim3(256, 1, 1);
    cfg.blockDim = dim3(512, 1, 1);
    cfg.dynamicSmemBytes = 0;
    cfg.stream = 0;
    cudaLaunchAttribute attrs[1];
    attrs[0].id = cudaLaunchAttributeProgrammaticStreamSerialization;
    attrs[0].val.programmaticStreamSerializationAllowed = 1;
    cfg.attrs = attrs;
    cfg.numAttrs = 1;
    cudaLaunchKernelEx(&cfg, gat_k2, adj, (float*)out);
}